// round 16
// baseline (speedup 1.0000x reference)
#include <cuda_runtime.h>
#include <cuda_bf16.h>
#include <cstdint>
#include <cstddef>

// ---------------------------------------------------------------------------
// Problem sizes: B=16, S=4096, D=1024, K=16, ITERS=3
// ---------------------------------------------------------------------------
#define SCALEF   0.03125f        /* 1024^-0.5 */
#define EPS_LN   1e-5f
#define EPS_ATTN 1e-8f

// fp32 scratch offsets (floats)
#define OFF_SLOTS 0u
#define OFF_GI    1572864u
#define OFF_GH    2359296u
#define OFF_WQT   4194304u
#define OFF_MFP   6291456u
#define OFF_U     10485760u     /* 262144 floats (atomic accum) */
#define OFF_WCB   10747904u
#define OFF_V2    10748928u
#define OFF_C0    10753024u
#define OFF_WKT   12582912u
#define OFF_CB    13631488u
#define OFF_BS    13631744u
#define OFF_RP    13632256u     /* 256 rows * 32 chunks */
#define OFF_ATTN  13640448u
#define SCRATCH_N 14689024u

__device__ float g_scratch[SCRATCH_N];

// bf16 2-plane weight buffers: [hi plane | lo plane], each N*K
__device__ __nv_bfloat16 g_wMw  [2u * 1024u * 1024u];
__device__ __nv_bfloat16 g_wV   [2u * 1024u * 1024u];
__device__ __nv_bfloat16 g_wIh  [2u * 3072u * 1024u];
__device__ __nv_bfloat16 g_wHh  [2u * 3072u * 1024u];
__device__ __nv_bfloat16 g_w1   [2u * 4096u * 1024u];
__device__ __nv_bfloat16 g_w2   [2u * 1024u * 4096u];
// one-time composition operands
__device__ __nv_bfloat16 g_wWqT [2u * 1024u * 1024u];
__device__ __nv_bfloat16 g_wWkT [2u * 1024u * 1024u];
// activation plane pairs
__device__ __nv_bfloat16 g_actAh[256u * 1024u], g_actAl[256u * 1024u];
__device__ __nv_bfloat16 g_actSh[256u * 1024u], g_actSl[256u * 1024u];
__device__ __nv_bfloat16 g_actBh[256u * 4096u], g_actBl[256u * 4096u];
// token planes [b][s][d] (written by iteration-0 fused pass)
__device__ __nv_bfloat16 g_tokh [16u * 4096u * 1024u];
__device__ __nv_bfloat16 g_tokl [16u * 4096u * 1024u];
// q2 planes [256][1024]
__device__ __nv_bfloat16 g_q2h[256u * 1024u];
__device__ __nv_bfloat16 g_q2l[256u * 1024u];

__device__ __forceinline__ float geluf(float x) {
    return 0.5f * x * (1.0f + erff(x * 0.70710678118654752f));
}
__device__ __forceinline__ float sigmf(float x) {
    return 1.0f / (1.0f + __expf(-x));
}

__device__ __forceinline__ uint32_t smem_u32(const void* p) {
    uint32_t a;
    asm("{ .reg .u64 t; cvta.to.shared.u64 t, %1; cvt.u32.u64 %0, t; }" : "=r"(a) : "l"(p));
    return a;
}
__device__ __forceinline__ void cp16s(uint32_t daddr, const void* src) {
    asm volatile("cp.async.cg.shared.global [%0], [%1], 16;" :: "r"(daddr), "l"(src));
}
__device__ __forceinline__ void cpcommit() {
    asm volatile("cp.async.commit_group;" ::: "memory");
}
__device__ __forceinline__ void cpwait_n(int n) {
    if (n <= 0)      asm volatile("cp.async.wait_group 0;" ::: "memory");
    else if (n == 1) asm volatile("cp.async.wait_group 1;" ::: "memory");
    else             asm volatile("cp.async.wait_group 2;" ::: "memory");
}
__device__ __forceinline__ void ldm4(uint32_t* r, uint32_t addr) {
    asm volatile("ldmatrix.sync.aligned.m8n8.x4.shared.b16 {%0,%1,%2,%3}, [%4];"
        : "=r"(r[0]), "=r"(r[1]), "=r"(r[2]), "=r"(r[3]) : "r"(addr));
}
__device__ __forceinline__ void ldm2(uint32_t* r, uint32_t addr) {
    asm volatile("ldmatrix.sync.aligned.m8n8.x2.shared.b16 {%0,%1}, [%2];"
        : "=r"(r[0]), "=r"(r[1]) : "r"(addr));
}
__device__ __forceinline__ void ldm2t(uint32_t* r, uint32_t addr) {
    asm volatile("ldmatrix.sync.aligned.m8n8.x2.trans.shared.b16 {%0,%1}, [%2];"
        : "=r"(r[0]), "=r"(r[1]) : "r"(addr));
}
__device__ __forceinline__ void mma16816(float* c, const uint32_t* a, const uint32_t* b) {
    asm volatile(
        "mma.sync.aligned.m16n8k16.row.col.f32.bf16.bf16.f32 "
        "{%0,%1,%2,%3}, {%4,%5,%6,%7}, {%8,%9}, {%0,%1,%2,%3};"
        : "+f"(c[0]), "+f"(c[1]), "+f"(c[2]), "+f"(c[3])
        : "r"(a[0]), "r"(a[1]), "r"(a[2]), "r"(a[3]), "r"(b[0]), "r"(b[1]));
}

__device__ __forceinline__ void bsplit(float x, __nv_bfloat16& h, __nv_bfloat16& l) {
    h = __float2bfloat16_rn(x);
    l = __float2bfloat16_rn(x - __bfloat162float(h));
}

// ---------------------------------------------------------------------------
// init: slots = broadcast(slot_mu); emit actS planes (slots feed gh at it0)
// ---------------------------------------------------------------------------
__global__ __launch_bounds__(256) void init_slots_kernel(const float* __restrict__ mu) {
    unsigned idx = blockIdx.x * 256u + threadIdx.x;          // < 262144
    float x = mu[idx & 16383u];
    g_scratch[OFF_SLOTS + idx] = x;
    __nv_bfloat16 h, l; bsplit(x, h, l);
    g_actSh[idx] = h; g_actSl[idx] = l;
}

// ---------------------------------------------------------------------------
// transpose 1024x1024 fp32: in -> g_scratch[dstOff]
// ---------------------------------------------------------------------------
__global__ void transpose_kernel(const float* __restrict__ in, unsigned dstOff) {
    __shared__ float t[32][33];
    int x  = blockIdx.x * 32 + threadIdx.x;
    int y0 = blockIdx.y * 32;
    #pragma unroll
    for (int j = threadIdx.y; j < 32; j += 8)
        t[j][threadIdx.x] = in[(size_t)(y0 + j) * 1024 + x];
    __syncthreads();
    int xo  = blockIdx.y * 32 + threadIdx.x;
    int yo0 = blockIdx.x * 32;
    #pragma unroll
    for (int j = threadIdx.y; j < 32; j += 8)
        g_scratch[dstOff + (size_t)(yo0 + j) * 1024 + xo] = t[threadIdx.x][j];
}

// ---------------------------------------------------------------------------
// split-convert to 2 planes: src (flat fp32) -> dh, dl
// ---------------------------------------------------------------------------
__global__ __launch_bounds__(256) void convw2_kernel(const float* __restrict__ src,
                                                     unsigned srcOff,
                                                     __nv_bfloat16* __restrict__ dh,
                                                     __nv_bfloat16* __restrict__ dl) {
    size_t idx4 = (size_t)blockIdx.x * 256u + threadIdx.x;
    const float* S = src ? src : (g_scratch + srcOff);
    float4 x = *(const float4*)(S + idx4 * 4);
    __nv_bfloat16 h0,h1,h2,h3,l0,l1,l2,l3;
    bsplit(x.x,h0,l0); bsplit(x.y,h1,l1); bsplit(x.z,h2,l2); bsplit(x.w,h3,l3);
    size_t k = idx4 * 4;
    *(__nv_bfloat162*)(dh + k)     = __nv_bfloat162(h0, h1);
    *(__nv_bfloat162*)(dh + k + 2) = __nv_bfloat162(h2, h3);
    *(__nv_bfloat162*)(dl + k)     = __nv_bfloat162(l0, l1);
    *(__nv_bfloat162*)(dl + k + 2) = __nv_bfloat162(l2, l3);
}

// ---------------------------------------------------------------------------
// gemv: out[row] = scale * dot(M[row, 0:len], v)
// ---------------------------------------------------------------------------
__global__ __launch_bounds__(256) void gemv_kernel(const float* __restrict__ M,
                                                   unsigned moff,
                                                   const float* __restrict__ v,
                                                   unsigned outoff, int len, float scale) {
    __shared__ float red[256];
    const float* Mr = (M ? M : g_scratch + moff) + (size_t)blockIdx.x * len;
    int tid = threadIdx.x;
    float p = 0.f;
    for (int i = tid * 4; i < len; i += 1024) {
        float4 a = *(const float4*)(Mr + i);
        float4 b = *(const float4*)(v + i);
        p += a.x*b.x + a.y*b.y + a.z*b.z + a.w*b.w;
    }
    red[tid] = p; __syncthreads();
    for (int o = 128; o > 0; o >>= 1) { if (tid < o) red[tid] += red[tid + o]; __syncthreads(); }
    if (tid == 0) g_scratch[outoff + blockIdx.x] = scale * red[0];
}

// ---------------------------------------------------------------------------
// 2-plane HMMA GEMM: C = (Ah+Al) (.) (Wh+Wl)^T  via Ah*Wh + Ah*Wl + Al*Wh.
// BM in {128, 64, 32}.  BN=64.  256 threads, 4-stage cp.async.
// epi: 0=+bias 2=gelu(+bias) 3=+bias+res(Cres) 4=*SCALE 6=raw
//      7=+bias+brow*bias2  8=+brow*bias
// ---------------------------------------------------------------------------
#define SAP 40

template<int BM>
__device__ __forceinline__ void gemm2_core(char* sm,
    const __nv_bfloat16* __restrict__ Ah, const __nv_bfloat16* __restrict__ Al,
    const __nv_bfloat16* __restrict__ Wh, const __nv_bfloat16* __restrict__ Wl,
    const float* __restrict__ bias, const float* __restrict__ bias2,
    float* Cout, const float* __restrict__ Cres,
    __nv_bfloat16* ph, __nv_bfloat16* pl,
    int N, int K, int epi)
{
    constexpr int NW_M = BM / 32;
    constexpr int WTN  = BM / 4;
    constexpr int NT   = WTN / 8;
    constexpr uint32_t AP  = BM * SAP * 2;
    constexpr uint32_t WP  = 64 * SAP * 2;
    constexpr uint32_t STG = 2 * AP + 2 * WP;

    const int tid  = threadIdx.x;
    const int lane = tid & 31, wid = tid >> 5;
    const int wm = (wid % NW_M) * 32;
    const int wn = (wid / NW_M) * WTN;
    const int bn = blockIdx.x * 64, bm = blockIdx.y * BM;
    const int NC = K >> 5;

    const uint32_t smb = smem_u32(sm);

    const int lrow = tid >> 2, lch = (tid & 3) * 8;
    const uint32_t aoff  = (uint32_t)(lrow * SAP + lch) * 2;
    const uint32_t aoff1 = (uint32_t)((64 + lrow) * SAP + lch) * 2;
    const __nv_bfloat16* agh0 = Ah + (size_t)(bm + (lrow < BM ? lrow : 0)) * K + lch;
    const __nv_bfloat16* agl0 = Al + (size_t)(bm + (lrow < BM ? lrow : 0)) * K + lch;
    const __nv_bfloat16* agh1 = Ah + (size_t)(bm + 64 + lrow) * K + lch;
    const __nv_bfloat16* agl1 = Al + (size_t)(bm + 64 + lrow) * K + lch;
    const __nv_bfloat16* wgh  = Wh + (size_t)(bn + lrow) * K + lch;
    const __nv_bfloat16* wgl  = Wl + (size_t)(bn + lrow) * K + lch;

    const int a_row = wm + (lane & 15);
    const int a_col = (lane >> 4) * 8;
    const int b_row = wn + ((lane >> 4) & 1) * 8 + (lane & 7);
    const int b_col = ((lane >> 3) & 1) * 8;
    const int l2 = lane & 15;
    const int b_row1 = wn + (l2 & 7);
    const int b_col1 = ((l2 >> 3) & 1) * 8;

    float acc[2][NT][4];
    #pragma unroll
    for (int i = 0; i < 2; i++)
        #pragma unroll
        for (int j = 0; j < NT; j++)
            #pragma unroll
            for (int e = 0; e < 4; e++) acc[i][j][e] = 0.f;

    auto load_stage = [&](int st, int c) {
        const uint32_t S = smb + (uint32_t)st * STG;
        const int ko = c * 32;
        if (BM >= 64 || lrow < BM) {
            cp16s(S + aoff, agh0 + ko);
            cp16s(S + AP + aoff, agl0 + ko);
        }
        if (BM == 128) {
            cp16s(S + aoff1, agh1 + ko);
            cp16s(S + AP + aoff1, agl1 + ko);
        }
        cp16s(S + 2 * AP + aoff, wgh + ko);
        cp16s(S + 2 * AP + WP + aoff, wgl + ko);
        cpcommit();
    };

    load_stage(0, 0);
    load_stage(1, 1);
    load_stage(2, 2);

    for (int c = 0; c < NC; c++) {
        int bnd = NC - 1 - c; if (bnd > 2) bnd = 2;
        cpwait_n(bnd);
        __syncthreads();
        if (c + 3 < NC) load_stage((c + 3) & 3, c + 3);
        const uint32_t S = smb + (uint32_t)(c & 3) * STG;
        const uint32_t abh = S, abl = S + AP;
        const uint32_t wbh = S + 2 * AP, wbl = S + 2 * AP + WP;
        #pragma unroll
        for (int ks = 0; ks < 2; ks++) {
            uint32_t afh[2][4], afl[2][4], bfh[2][4], bfl[2][4];
            #pragma unroll
            for (int mt = 0; mt < 2; mt++) {
                uint32_t ao = (uint32_t)(((a_row + mt * 16) * SAP) + ks * 16 + a_col) * 2;
                ldm4(afh[mt], abh + ao);
                ldm4(afl[mt], abl + ao);
            }
            if (NT == 1) {
                uint32_t bo = (uint32_t)((b_row1 * SAP) + ks * 16 + b_col1) * 2;
                ldm2(bfh[0], wbh + bo);
                ldm2(bfl[0], wbl + bo);
            } else {
                #pragma unroll
                for (int nb = 0; nb < NT / 2; nb++) {
                    uint32_t bo = (uint32_t)(((b_row + nb * 16) * SAP) + ks * 16 + b_col) * 2;
                    ldm4(bfh[nb], wbh + bo);
                    ldm4(bfl[nb], wbl + bo);
                }
            }
            #pragma unroll
            for (int mt = 0; mt < 2; mt++)
                #pragma unroll
                for (int nt = 0; nt < NT; nt++) {
                    const uint32_t* bh = &bfh[nt >> 1][(nt & 1) * 2];
                    const uint32_t* bl = &bfl[nt >> 1][(nt & 1) * 2];
                    mma16816(acc[mt][nt], afh[mt], bh);
                    mma16816(acc[mt][nt], afh[mt], bl);
                    mma16816(acc[mt][nt], afl[mt], bh);
                }
        }
    }

    const int mrow = lane >> 2, ncol2 = (lane & 3) * 2;
    #pragma unroll
    for (int mt = 0; mt < 2; mt++) {
        #pragma unroll
        for (int h = 0; h < 2; h++) {
            const int m = bm + wm + mt * 16 + mrow + h * 8;
            float brow = 0.f;
            if (epi == 7 || epi == 8) brow = g_scratch[OFF_BS + m];
            #pragma unroll
            for (int nt = 0; nt < NT; nt++) {
                const int n0 = bn + wn + nt * 8 + ncol2;
                float ox = acc[mt][nt][h * 2], oy = acc[mt][nt][h * 2 + 1];
                if (epi == 4) { ox *= SCALEF; oy *= SCALEF; }
                else if (epi == 6) { }
                else {
                    float2 bb = *(const float2*)(bias + n0);
                    if (epi == 7) {
                        float2 b2 = *(const float2*)(bias2 + n0);
                        ox += bb.x + brow * b2.x; oy += bb.y + brow * b2.y;
                    } else if (epi == 8) {
                        ox += brow * bb.x; oy += brow * bb.y;
                    } else { ox += bb.x; oy += bb.y; }
                    if (epi == 2) { ox = geluf(ox); oy = geluf(oy); }
                    if (epi == 3) {
                        float2 c0 = *(const float2*)(Cres + (size_t)m * N + n0);
                        ox += c0.x; oy += c0.y;
                    }
                }
                if (Cout) *(float2*)(Cout + (size_t)m * N + n0) = make_float2(ox, oy);
                if (ph) {
                    __nv_bfloat16 hx, lx, hy, ly;
                    bsplit(ox, hx, lx); bsplit(oy, hy, ly);
                    *(__nv_bfloat162*)(ph + (size_t)m * N + n0) = __nv_bfloat162(hx, hy);
                    *(__nv_bfloat162*)(pl + (size_t)m * N + n0) = __nv_bfloat162(lx, ly);
                }
            }
        }
    }
}

template<int BM>
__global__ __launch_bounds__(256) void gemm2_k(const __nv_bfloat16* __restrict__ Ah,
                                               const __nv_bfloat16* __restrict__ Al,
                                               const __nv_bfloat16* __restrict__ Wh,
                                               const __nv_bfloat16* __restrict__ Wl,
                                               const float* __restrict__ bias,
                                               const float* __restrict__ bias2,
                                               float* Cout, const float* Cres,
                                               __nv_bfloat16* ph, __nv_bfloat16* pl,
                                               int N, int K, int epi) {
    extern __shared__ char sm[];
    gemm2_core<BM>(sm, Ah, Al, Wh, Wl, bias, bias2, Cout, Cres, ph, pl, N, K, epi);
}

// merged GRU gemms (BM=64: 2 CTAs/SM)
__global__ __launch_bounds__(256) void gru_gemm_k(const float* __restrict__ bih,
                                                  const float* __restrict__ bhh) {
    extern __shared__ char sm[];
    if (blockIdx.z == 0)
        gemm2_core<64>(sm, g_actBh, g_actBl, g_wIh, g_wIh + 3072u*1024u,
                       bih, nullptr, g_scratch + OFF_GI, nullptr,
                       nullptr, nullptr, 3072, 1024, 0);
    else
        gemm2_core<64>(sm, g_actSh, g_actSl, g_wHh, g_wHh + 3072u*1024u,
                       bhh, nullptr, g_scratch + OFF_GH, nullptr,
                       nullptr, nullptr, 3072, 1024, 0);
}

// ---------------------------------------------------------------------------
// Single-read fused pass (256 threads): per 16-token group -- get tok strip
// (conv: fp32 load + split + plane writeback; else: cp.async from planes),
// logits (k split over 8 warps) + shfl softmax + updates vs SAME strip.
// U accumulated in registers across groups; one atomicAdd set per CTA.
// grid (32 chunks of 128 tokens, 16 b).
// ---------------------------------------------------------------------------
#define FP_SMEM 198144
__global__ __launch_bounds__(256) void fused_pass_kernel(const float* __restrict__ tokens,
                                                         float* __restrict__ attn_out,
                                                         int wlast, int conv) {
    extern __shared__ char sm[];
    __shared__ float Lg[8][16][17];
    __shared__ float Att32[16][17];                 // [token][slot]
    __shared__ __nv_bfloat16 ATh[16][24], ATl[16][24];  // [slot][token]
    __shared__ float cbs[16], rs[16];
    const int tid = threadIdx.x;
    const int lane = tid & 31, wid = tid >> 5;
    const int sc = blockIdx.x, b = blockIdx.y;

    const uint32_t smb = smem_u32(sm);
    const uint32_t Qh = smb, Ql = smb + 33024u;
    const uint32_t TB = smb + 66048u;               // 2 buffers x 66048

    if (tid < 16) { cbs[tid] = g_scratch[OFF_CB + b * 16 + tid]; rs[tid] = 0.f; }

    const size_t tokbase = ((size_t)b * 4096 + (size_t)sc * 128) * 1024;

    auto load_group = [&](int buf, int g) {
        const uint32_t Bs = TB + (uint32_t)buf * 66048u;
        #pragma unroll
        for (int i = 0; i < 8; i++) {
            int idx = tid + 256 * i;
            int row = idx >> 7, j = idx & 127;
            cp16s(Bs + (uint32_t)(row * 1032 + j * 8) * 2,
                  g_tokh + tokbase + (size_t)(g * 16 + row) * 1024 + j * 8);
            cp16s(Bs + 33024u + (uint32_t)(row * 1032 + j * 8) * 2,
                  g_tokl + tokbase + (size_t)(g * 16 + row) * 1024 + j * 8);
        }
        cpcommit();
    };

    // conv: load fp32 tokens, split in registers, write smem planes + gmem planes
    auto conv_group = [&](int buf, int g) {
        char* Bp = sm + 66048u + (size_t)buf * 66048u;
        const int c4 = tid * 4;
        #pragma unroll
        for (int row = 0; row < 16; row++) {
            size_t go = tokbase + (size_t)(g * 16 + row) * 1024 + c4;
            float4 x = *(const float4*)(tokens + go);
            __nv_bfloat16 h0,h1,h2,h3,l0,l1,l2,l3;
            bsplit(x.x,h0,l0); bsplit(x.y,h1,l1); bsplit(x.z,h2,l2); bsplit(x.w,h3,l3);
            size_t so = (size_t)(row * 1032 + c4) * 2;
            *(__nv_bfloat162*)(Bp + so)              = __nv_bfloat162(h0, h1);
            *(__nv_bfloat162*)(Bp + so + 4)          = __nv_bfloat162(h2, h3);
            *(__nv_bfloat162*)(Bp + 33024u + so)     = __nv_bfloat162(l0, l1);
            *(__nv_bfloat162*)(Bp + 33024u + so + 4) = __nv_bfloat162(l2, l3);
            *(__nv_bfloat162*)(g_tokh + go)     = __nv_bfloat162(h0, h1);
            *(__nv_bfloat162*)(g_tokh + go + 2) = __nv_bfloat162(h2, h3);
            *(__nv_bfloat162*)(g_tokl + go)     = __nv_bfloat162(l0, l1);
            *(__nv_bfloat162*)(g_tokl + go + 2) = __nv_bfloat162(l2, l3);
        }
    };

    // Q planes (+ first group if not conv)
    {
        #pragma unroll
        for (int i = 0; i < 8; i++) {
            int id = tid + 256 * i;
            int row = id >> 7, j = id & 127;
            cp16s(Qh + (uint32_t)(row * 1032 + j * 8) * 2,
                  g_q2h + (size_t)(b * 16 + row) * 1024 + j * 8);
            cp16s(Ql + (uint32_t)(row * 1032 + j * 8) * 2,
                  g_q2l + (size_t)(b * 16 + row) * 1024 + j * 8);
        }
        cpcommit();
        if (!conv) load_group(0, 0);
    }
    if (conv) { cpwait_n(0); __syncthreads(); }   // Q ready for conv path

    // persistent U accumulators: warp wid owns d slice [wid*128, wid*128+128)
    float uacc[16][4];
    #pragma unroll
    for (int nt = 0; nt < 16; nt++)
        #pragma unroll
        for (int e = 0; e < 4; e++) uacc[nt][e] = 0.f;

    const int kw = wid * 128;               // this warp's k-slice
    const int a_r = lane & 15;              // token row
    const int a_c = (lane >> 4) * 8;
    const int b_r = ((lane >> 4) & 1) * 8 + (lane & 7);
    const int b_c = ((lane >> 3) & 1) * 8;
    const uint32_t ATHb = smem_u32(&ATh[0][0]);
    const uint32_t ATLb = smem_u32(&ATl[0][0]);
    const uint32_t at_off = (uint32_t)((lane & 15) * 24 + (lane >> 4) * 8) * 2;

    for (int g = 0; g < 8; g++) {
        if (conv) {
            __syncthreads();                // prior compute done reading buffer
            conv_group(g & 1, g);
            __syncthreads();
        } else {
            cpwait_n(0);
            __syncthreads();
            if (g + 1 < 8) load_group((g + 1) & 1, g + 1);
        }
        const uint32_t Bs = TB + (uint32_t)(g & 1) * 66048u;
        const uint32_t Bh = Bs, Bl = Bs + 33024u;

        // ---- logits: warp k-slice, m16 (tokens) x n16 (slots) ----
        float la[2][4];
        #pragma unroll
        for (int nt = 0; nt < 2; nt++)
            #pragma unroll
            for (int e = 0; e < 4; e++) la[nt][e] = 0.f;
        #pragma unroll
        for (int ks = 0; ks < 8; ks++) {
            const int col = kw + ks * 16;
            uint32_t afh[4], afl[4], bfh[4], bfl[4];
            uint32_t ao = (uint32_t)(a_r * 1032 + col + a_c) * 2;
            ldm4(afh, Bh + ao);
            ldm4(afl, Bl + ao);
            uint32_t bo = (uint32_t)(b_r * 1032 + col + b_c) * 2;
            ldm4(bfh, Qh + bo);
            ldm4(bfl, Ql + bo);
            #pragma unroll
            for (int nt = 0; nt < 2; nt++) {
                mma16816(la[nt], afh, &bfh[nt * 2]);
                mma16816(la[nt], afh, &bfl[nt * 2]);
                mma16816(la[nt], afl, &bfh[nt * 2]);
            }
        }
        #pragma unroll
        for (int nt = 0; nt < 2; nt++)
            #pragma unroll
            for (int e = 0; e < 4; e++) {
                int row = (lane >> 2) + (e >> 1) * 8;
                int col = nt * 8 + (lane & 3) * 2 + (e & 1);
                Lg[wid][row][col] = la[nt][e];
            }
        __syncthreads();

        // ---- fused reduce + parallel softmax (256 thr = 16 tok x 16 slot) ----
        {
            int tok = tid >> 4, s = tid & 15;
            float v = cbs[s];
            #pragma unroll
            for (int w = 0; w < 8; w++) v += Lg[w][tok][s];
            float mx = v;
            #pragma unroll
            for (int o = 8; o > 0; o >>= 1)
                mx = fmaxf(mx, __shfl_xor_sync(0xffffffffu, mx, o));
            float e = __expf(v - mx);
            float sum = e;
            #pragma unroll
            for (int o = 8; o > 0; o >>= 1)
                sum += __shfl_xor_sync(0xffffffffu, sum, o);
            float a = e / sum;
            Att32[tok][s] = a;
            __nv_bfloat16 h, l; bsplit(a, h, l);
            ATh[s][tok] = h; ATl[s][tok] = l;
            if (wlast)
                attn_out[(size_t)(b * 16 + s) * 4096 + (size_t)sc * 128 + g * 16 + tok] = a;
        }
        __syncthreads();

        // rowsum partial (threads 16..31, slot = tid-16)
        if (tid >= 16 && tid < 32) {
            int s = tid - 16;
            float t = 0.f;
            #pragma unroll
            for (int tok = 0; tok < 16; tok++) t += Att32[tok][s];
            rs[s] += t;
        }

        // ---- updates: U[slots][d-slice] += attnT @ tok  (same strip) ----
        uint32_t ath[4], atl[4];
        ldm4(ath, ATHb + at_off);
        ldm4(atl, ATLb + at_off);
        #pragma unroll
        for (int nt = 0; nt < 16; nt++) {
            const int d0 = kw + nt * 8;
            uint32_t bh[2], bl[2];
            uint32_t bo = (uint32_t)((lane & 15) * 1032 + d0) * 2;
            ldm2t(bh, Bh + bo);
            ldm2t(bl, Bl + bo);
            mma16816(uacc[nt], ath, bh);
            mma16816(uacc[nt], ath, bl);
            mma16816(uacc[nt], atl, bh);
        }
    }

    __syncthreads();
    if (tid < 16)
        g_scratch[OFF_RP + (size_t)(b * 16 + tid) * 32 + sc] = rs[tid];

    // one atomic accumulation per CTA
    float* Ub = g_scratch + OFF_U + (size_t)(b * 16) * 1024;
    const int slot0 = lane >> 2;
    #pragma unroll
    for (int nt = 0; nt < 16; nt++) {
        const int d0 = kw + nt * 8 + (lane & 3) * 2;
        atomicAdd(&Ub[(size_t)slot0 * 1024 + d0],           uacc[nt][0]);
        atomicAdd(&Ub[(size_t)slot0 * 1024 + d0 + 1],       uacc[nt][1]);
        atomicAdd(&Ub[(size_t)(slot0 + 8) * 1024 + d0],     uacc[nt][2]);
        atomicAdd(&Ub[(size_t)(slot0 + 8) * 1024 + d0 + 1], uacc[nt][3]);
    }
}

// ---------------------------------------------------------------------------
// LayerNorm (slots) -> actA planes; docb=1: also cb + zero-U
// ---------------------------------------------------------------------------
__global__ __launch_bounds__(256) void ln_kernel(unsigned offX,
                                                 const float* __restrict__ g,
                                                 const float* __restrict__ bt,
                                                 int docb) {
    __shared__ float red[256];
    const float* X = g_scratch + offX;
    int row = blockIdx.x, tid = threadIdx.x;
    float4 x = ((const float4*)X)[row * 256 + tid];
    red[tid] = x.x + x.y + x.z + x.w;
    __syncthreads();
    for (int o = 128; o > 0; o >>= 1) { if (tid < o) red[tid] += red[tid + o]; __syncthreads(); }
    float mean = red[0] * (1.0f / 1024.0f);
    __syncthreads();
    float4 dx = { x.x - mean, x.y - mean, x.z - mean, x.w - mean };
    red[tid] = dx.x*dx.x + dx.y*dx.y + dx.z*dx.z + dx.w*dx.w;
    __syncthreads();
    for (int o = 128; o > 0; o >>= 1) { if (tid < o) red[tid] += red[tid + o]; __syncthreads(); }
    float rs = rsqrtf(red[0] * (1.0f / 1024.0f) + EPS_LN);
    float4 gg = ((const float4*)g)[tid], bb = ((const float4*)bt)[tid];
    float y[4] = { dx.x*rs*gg.x + bb.x, dx.y*rs*gg.y + bb.y,
                   dx.z*rs*gg.z + bb.z, dx.w*rs*gg.w + bb.w };
    size_t base = (size_t)row * 1024u + tid * 4;
    #pragma unroll
    for (int j = 0; j < 4; j++) {
        __nv_bfloat16 h, l; bsplit(y[j], h, l);
        g_actAh[base + j] = h; g_actAl[base + j] = l;
    }
    if (docb) {
        *(float4*)&g_scratch[OFF_U + base] = make_float4(0.f, 0.f, 0.f, 0.f);
        float p = 0.f;
        #pragma unroll
        for (int j = 0; j < 4; j++) p += y[j] * g_scratch[OFF_WCB + tid * 4 + j];
        __syncthreads();
        red[tid] = p; __syncthreads();
        for (int o = 128; o > 0; o >>= 1) { if (tid < o) red[tid] += red[tid + o]; __syncthreads(); }
        if (tid == 0)
            g_scratch[OFF_CB + row] = SCALEF * (red[0] + g_scratch[OFF_C0]);
    }
}

// ---------------------------------------------------------------------------
// reduceU (+rowsum): Un[row] = U[row]/rowsum -> actA planes; BS=brow
// ---------------------------------------------------------------------------
__global__ __launch_bounds__(256) void reduceU_kernel() {
    float* S = g_scratch;
    int row = blockIdx.x, tid = threadIdx.x;
    float s = 0.f;
    #pragma unroll
    for (int cc = 0; cc < 32; cc++) s += S[OFF_RP + (size_t)row * 32 + cc];
    float ri = 1.0f / (s + EPS_ATTN);
    if (tid == 0) S[OFF_BS + row] = s * ri;
    size_t base = (size_t)row * 1024u + tid * 4;
    float4 v = *(const float4*)&S[OFF_U + base];
    float y[4] = { v.x * ri, v.y * ri, v.z * ri, v.w * ri };
    #pragma unroll
    for (int j = 0; j < 4; j++) {
        __nv_bfloat16 h, l; bsplit(y[j], h, l);
        g_actAh[base + j] = h; g_actAl[base + j] = l;
    }
}

// ---------------------------------------------------------------------------
// Fused GRU combine + LayerNorm(mlp) -> slots, actA planes.  block = row.
// ---------------------------------------------------------------------------
__global__ __launch_bounds__(256) void gru_ln_kernel(const float* __restrict__ gm,
                                                     const float* __restrict__ bm) {
    __shared__ float red[256];
    float* S = g_scratch;
    int row = blockIdx.x, tid = threadIdx.x;
    size_t gb = (size_t)row * 3072 + tid * 4;
    float4 ir = *(const float4*)&S[OFF_GI + gb];
    float4 iz = *(const float4*)&S[OFF_GI + gb + 1024];
    float4 in_ = *(const float4*)&S[OFF_GI + gb + 2048];
    float4 hr = *(const float4*)&S[OFF_GH + gb];
    float4 hz = *(const float4*)&S[OFF_GH + gb + 1024];
    float4 hn = *(const float4*)&S[OFF_GH + gb + 2048];
    float4 sp = *(const float4*)&S[OFF_SLOTS + (size_t)row * 1024 + tid * 4];
    float ns[4];
    {
        float r0 = sigmf(ir.x + hr.x), z0 = sigmf(iz.x + hz.x);
        ns[0] = (1.f - z0) * tanhf(in_.x + r0 * hn.x) + z0 * sp.x;
        float r1 = sigmf(ir.y + hr.y), z1 = sigmf(iz.y + hz.y);
        ns[1] = (1.f - z1) * tanhf(in_.y + r1 * hn.y) + z1 * sp.y;
        float r2 = sigmf(ir.z + hr.z), z2 = sigmf(iz.z + hz.z);
        ns[2] = (1.f - z2) * tanhf(in_.z + r2 * hn.z) + z2 * sp.z;
        float r3 = sigmf(ir.w + hr.w), z3 = sigmf(iz.w + hz.w);
        ns[3] = (1.f - z3) * tanhf(in_.w + r3 * hn.w) + z3 * sp.w;
    }
    *(float4*)&S[OFF_SLOTS + (size_t)row * 1024 + tid * 4] =
        make_float4(ns[0], ns[1], ns[2], ns[3]);
    red[tid] = ns[0] + ns[1] + ns[2] + ns[3];
    __syncthreads();
    for (int o = 128; o > 0; o >>= 1) { if (tid < o) red[tid] += red[tid + o]; __syncthreads(); }
    float mean = red[0] * (1.0f / 1024.0f);
    __syncthreads();
    float dx[4] = { ns[0]-mean, ns[1]-mean, ns[2]-mean, ns[3]-mean };
    red[tid] = dx[0]*dx[0] + dx[1]*dx[1] + dx[2]*dx[2] + dx[3]*dx[3];
    __syncthreads();
    for (int o = 128; o > 0; o >>= 1) { if (tid < o) red[tid] += red[tid + o]; __syncthreads(); }
    float rs = rsqrtf(red[0] * (1.0f / 1024.0f) + EPS_LN);
    float4 gg = ((const float4*)gm)[tid], bb = ((const float4*)bm)[tid];
    float y[4] = { dx[0]*rs*gg.x + bb.x, dx[1]*rs*gg.y + bb.y,
                   dx[2]*rs*gg.z + bb.z, dx[3]*rs*gg.w + bb.w };
    size_t base = (size_t)row * 1024u + tid * 4;
    #pragma unroll
    for (int j = 0; j < 4; j++) {
        __nv_bfloat16 h, l; bsplit(y[j], h, l);
        g_actAh[base + j] = h; g_actAl[base + j] = l;
    }
}

// ---------------------------------------------------------------------------
// copy slots -> out (fallback only)
// ---------------------------------------------------------------------------
__global__ __launch_bounds__(256) void copy_out_kernel(float* __restrict__ out, int n) {
    int idx = blockIdx.x * 256 + threadIdx.x;
    if (idx < n) out[idx] = g_scratch[OFF_SLOTS + idx];
}

// ---------------------------------------------------------------------------
// host
// ---------------------------------------------------------------------------
#define SMEM128 (4 * (2*128 + 2*64) * SAP * 2)   /* 122880 */
#define SMEM64  (4 * (2*64 + 2*64) * SAP * 2)    /* 81920 */
#define SMEM32  (4 * (2*32 + 2*64) * SAP * 2)    /* 61440 */

extern "C" void kernel_launch(void* const* d_in, const int* in_sizes, int n_in,
                              void* d_out, int out_size) {
    const float* tokens = (const float*)d_in[0];
    const float* mu     = (const float*)d_in[1];
    const float* Wq  = (const float*)d_in[2];  const float* bq  = (const float*)d_in[3];
    const float* Wk  = (const float*)d_in[4];  const float* bk  = (const float*)d_in[5];
    const float* Wv  = (const float*)d_in[6];  const float* bv  = (const float*)d_in[7];
    const float* Wih = (const float*)d_in[8];  const float* bih = (const float*)d_in[9];
    const float* Whh = (const float*)d_in[10]; const float* bhh = (const float*)d_in[11];
    const float* W1  = (const float*)d_in[12]; const float* b1  = (const float*)d_in[13];
    const float* W2  = (const float*)d_in[14]; const float* b2  = (const float*)d_in[15];
    const float* gs  = (const float*)d_in[16]; const float* bs  = (const float*)d_in[17];
    const float* gm  = (const float*)d_in[18]; const float* bm  = (const float*)d_in[19];
    float* out = (float*)d_out;

    cudaFuncSetAttribute((const void*)gemm2_k<128>, cudaFuncAttributeMaxDynamicSharedMemorySize, SMEM128);
    cudaFuncSetAttribute((const void*)gemm2_k<64>,  cudaFuncAttributeMaxDynamicSharedMemorySize, SMEM64);
    cudaFuncSetAttribute((const void*)gemm2_k<32>,  cudaFuncAttributeMaxDynamicSharedMemorySize, SMEM32);
    cudaFuncSetAttribute((const void*)gru_gemm_k,   cudaFuncAttributeMaxDynamicSharedMemorySize, SMEM64);
    cudaFuncSetAttribute((const void*)fused_pass_kernel, cudaFuncAttributeMaxDynamicSharedMemorySize, FP_SMEM);

    __nv_bfloat16 *wMw, *wV, *wIh, *wHh, *w1, *w2, *wWqT, *wWkT;
    __nv_bfloat16 *actAh, *actAl, *actBh, *actBl, *q2h, *q2l, *actSh, *actSl;
    cudaGetSymbolAddress((void**)&wMw,  g_wMw);
    cudaGetSymbolAddress((void**)&wV,   g_wV);
    cudaGetSymbolAddress((void**)&wIh,  g_wIh);
    cudaGetSymbolAddress((void**)&wHh,  g_wHh);
    cudaGetSymbolAddress((void**)&w1,   g_w1);
    cudaGetSymbolAddress((void**)&w2,   g_w2);
    cudaGetSymbolAddress((void**)&wWqT, g_wWqT);
    cudaGetSymbolAddress((void**)&wWkT, g_wWkT);
    cudaGetSymbolAddress((void**)&actAh, g_actAh);
    cudaGetSymbolAddress((void**)&actAl, g_actAl);
    cudaGetSymbolAddress((void**)&actBh, g_actBh);
    cudaGetSymbolAddress((void**)&actBl, g_actBl);
    cudaGetSymbolAddress((void**)&q2h, g_q2h);
    cudaGetSymbolAddress((void**)&q2l, g_q2l);
    cudaGetSymbolAddress((void**)&actSh, g_actSh);
    cudaGetSymbolAddress((void**)&actSl, g_actSl);
    float* scr;
    cudaGetSymbolAddress((void**)&scr, g_scratch);

    const int direct_out = (out_size >= 262144);
    float* attnp = (out_size >= 1310720) ? (out + 262144) : (scr + OFF_ATTN);

    const size_t P1M = 1024u * 1024u;
    const size_t P3M = 3072u * 1024u;
    const size_t P4M = 4096u * 1024u;

    // ---- one-time ----
    transpose_kernel<<<dim3(32, 32), dim3(32, 8)>>>(Wk, OFF_WKT);
    transpose_kernel<<<dim3(32, 32), dim3(32, 8)>>>(Wq, OFF_WQT);
    convw2_kernel<<<1024, 256>>>(nullptr, OFF_WQT, wWqT, wWqT + P1M);
    convw2_kernel<<<1024, 256>>>(nullptr, OFF_WKT, wWkT, wWkT + P1M);
    convw2_kernel<<<1024, 256>>>(Wv,  0, wV,  wV + P1M);
    convw2_kernel<<<3072, 256>>>(Wih, 0, wIh, wIh + P3M);
    gemv_kernel<<<1024, 256>>>(nullptr, OFF_WQT, bk, OFF_WCB, 1024, 1.0f);
    gemv_kernel<<<1024, 256>>>(nullptr, OFF_WKT, bq, OFF_V2, 1024, SCALEF);
    gemv_kernel<<<1, 256>>>(bq, 0, bk, OFF_C0, 1024, 1.0f);
    // Mw = SCALE * WkT (.) WqT^T   [1024 x 1024]
    gemm2_k<128><<<dim3(16, 8), 256, SMEM128>>>(wWkT, wWkT + P1M, wWqT, wWqT + P1M,
                                                nullptr, nullptr, scr + OFF_MFP, nullptr,
                                                nullptr, nullptr, 1024, 1024, 4);
    convw2_kernel<<<1024, 256>>>(nullptr, OFF_MFP, wMw, wMw + P1M);
    convw2_kernel<<<3072, 256>>>(Whh, 0, wHh, wHh + P3M);
    convw2_kernel<<<4096, 256>>>(W1,  0, w1,  w1 + P4M);
    convw2_kernel<<<4096, 256>>>(W2,  0, w2,  w2 + P4M);
    init_slots_kernel<<<1024, 256>>>(mu);

    for (int it = 0; it < 3; it++) {
        const int last = (it == 2);
        ln_kernel<<<256, 256>>>(OFF_SLOTS, gs, bs, 1);
        gemm2_k<32><<<dim3(16, 8), 256, SMEM32>>>(actAh, actAl, wMw, wMw + P1M,
                                                  scr + OFF_V2, nullptr, nullptr, nullptr,
                                                  q2h, q2l, 1024, 1024, 0);
        fused_pass_kernel<<<dim3(32, 16), 256, FP_SMEM>>>(tokens, attnp, last, it == 0);
        reduceU_kernel<<<256, 256>>>();
        // upd = Un @ Wv^T + brow*bv  -> actB planes
        gemm2_k<32><<<dim3(16, 8), 256, SMEM32>>>(actAh, actAl, wV, wV + P1M,
                                                  bv, nullptr, nullptr, nullptr,
                                                  actBh, actBl, 1024, 1024, 8);
        gru_gemm_k<<<dim3(48, 4, 2), 256, SMEM64>>>(bih, bhh);
        gru_ln_kernel<<<256, 256>>>(gm, bm);
        gemm2_k<64><<<dim3(64, 4), 256, SMEM64>>>(actAh, actAl, w1, w1 + P4M,
                                                  b1, nullptr, nullptr, nullptr,
                                                  actBh, actBl, 4096, 1024, 2);
        float* w2dst = (last && direct_out) ? out : (scr + OFF_SLOTS);
        gemm2_k<32><<<dim3(16, 8), 256, SMEM32>>>(actBh, actBl, w2, w2 + P4M,
                                                  b2, nullptr, w2dst, scr + OFF_SLOTS,
                                                  last ? nullptr : actSh,
                                                  last ? nullptr : actSl,
                                                  1024, 4096, 3);
    }

    if (!direct_out) {
        int nslots = out_size < 262144 ? out_size : 262144;
        copy_out_kernel<<<1024, 256>>>(out, nslots);
    }
}

// round 17
// speedup vs baseline: 1.0247x; 1.0247x over previous
#include <cuda_runtime.h>
#include <cuda_bf16.h>
#include <cstdint>
#include <cstddef>

// ---------------------------------------------------------------------------
// Problem sizes: B=16, S=4096, D=1024, K=16, ITERS=3
// ---------------------------------------------------------------------------
#define SCALEF   0.03125f        /* 1024^-0.5 */
#define EPS_LN   1e-5f
#define EPS_ATTN 1e-8f

// fp32 scratch offsets (floats)
#define OFF_SLOTS 0u
#define OFF_GI    1572864u
#define OFF_GH    2359296u
#define OFF_WQT   4194304u
#define OFF_MFP   6291456u
#define OFF_U     10485760u     /* 262144 floats (atomic accum) */
#define OFF_WCB   10747904u
#define OFF_V2    10748928u
#define OFF_C0    10753024u
#define OFF_WKT   12582912u
#define OFF_CB    13631488u
#define OFF_BS    13631744u
#define OFF_RP    13632256u     /* 256 rows * 32 chunks */
#define OFF_ATTN  13640448u
#define SCRATCH_N 14689024u

__device__ float g_scratch[SCRATCH_N];

// bf16 2-plane weight buffers: [hi plane | lo plane], each N*K
__device__ __nv_bfloat16 g_wMw  [2u * 1024u * 1024u];
__device__ __nv_bfloat16 g_wV   [2u * 1024u * 1024u];
__device__ __nv_bfloat16 g_wIh  [2u * 3072u * 1024u];
__device__ __nv_bfloat16 g_wHh  [2u * 3072u * 1024u];
__device__ __nv_bfloat16 g_w1   [2u * 4096u * 1024u];
__device__ __nv_bfloat16 g_w2   [2u * 1024u * 4096u];
// one-time composition operands
__device__ __nv_bfloat16 g_wWqT [2u * 1024u * 1024u];
__device__ __nv_bfloat16 g_wWkT [2u * 1024u * 1024u];
// activation plane pairs
__device__ __nv_bfloat16 g_actAh[256u * 1024u], g_actAl[256u * 1024u];
__device__ __nv_bfloat16 g_actSh[256u * 1024u], g_actSl[256u * 1024u];
__device__ __nv_bfloat16 g_actBh[256u * 4096u], g_actBl[256u * 4096u];
// token planes [b][s][d]
__device__ __nv_bfloat16 g_tokh [16u * 4096u * 1024u];
__device__ __nv_bfloat16 g_tokl [16u * 4096u * 1024u];
// q2 planes [256][1024]
__device__ __nv_bfloat16 g_q2h[256u * 1024u];
__device__ __nv_bfloat16 g_q2l[256u * 1024u];

__device__ __forceinline__ float geluf(float x) {
    return 0.5f * x * (1.0f + erff(x * 0.70710678118654752f));
}
__device__ __forceinline__ float sigmf(float x) {
    return 1.0f / (1.0f + __expf(-x));
}

__device__ __forceinline__ uint32_t smem_u32(const void* p) {
    uint32_t a;
    asm("{ .reg .u64 t; cvta.to.shared.u64 t, %1; cvt.u32.u64 %0, t; }" : "=r"(a) : "l"(p));
    return a;
}
__device__ __forceinline__ void cp16s(uint32_t daddr, const void* src) {
    asm volatile("cp.async.cg.shared.global [%0], [%1], 16;" :: "r"(daddr), "l"(src));
}
__device__ __forceinline__ void cpcommit() {
    asm volatile("cp.async.commit_group;" ::: "memory");
}
__device__ __forceinline__ void cpwait_n(int n) {
    if (n <= 0)      asm volatile("cp.async.wait_group 0;" ::: "memory");
    else if (n == 1) asm volatile("cp.async.wait_group 1;" ::: "memory");
    else             asm volatile("cp.async.wait_group 2;" ::: "memory");
}
__device__ __forceinline__ void ldm4(uint32_t* r, uint32_t addr) {
    asm volatile("ldmatrix.sync.aligned.m8n8.x4.shared.b16 {%0,%1,%2,%3}, [%4];"
        : "=r"(r[0]), "=r"(r[1]), "=r"(r[2]), "=r"(r[3]) : "r"(addr));
}
__device__ __forceinline__ void ldm2(uint32_t* r, uint32_t addr) {
    asm volatile("ldmatrix.sync.aligned.m8n8.x2.shared.b16 {%0,%1}, [%2];"
        : "=r"(r[0]), "=r"(r[1]) : "r"(addr));
}
__device__ __forceinline__ void ldm2t(uint32_t* r, uint32_t addr) {
    asm volatile("ldmatrix.sync.aligned.m8n8.x2.trans.shared.b16 {%0,%1}, [%2];"
        : "=r"(r[0]), "=r"(r[1]) : "r"(addr));
}
__device__ __forceinline__ void mma16816(float* c, const uint32_t* a, const uint32_t* b) {
    asm volatile(
        "mma.sync.aligned.m16n8k16.row.col.f32.bf16.bf16.f32 "
        "{%0,%1,%2,%3}, {%4,%5,%6,%7}, {%8,%9}, {%0,%1,%2,%3};"
        : "+f"(c[0]), "+f"(c[1]), "+f"(c[2]), "+f"(c[3])
        : "r"(a[0]), "r"(a[1]), "r"(a[2]), "r"(a[3]), "r"(b[0]), "r"(b[1]));
}

__device__ __forceinline__ void bsplit(float x, __nv_bfloat16& h, __nv_bfloat16& l) {
    h = __float2bfloat16_rn(x);
    l = __float2bfloat16_rn(x - __bfloat162float(h));
}

// block reduce (256 threads): returns total to ALL threads. red must be >=8 floats.
__device__ __forceinline__ float blk_reduce(float v, float* red, int tid) {
    #pragma unroll
    for (int o = 16; o > 0; o >>= 1)
        v += __shfl_xor_sync(0xffffffffu, v, o);
    if ((tid & 31) == 0) red[tid >> 5] = v;
    __syncthreads();
    float t = red[0] + red[1] + red[2] + red[3] +
              red[4] + red[5] + red[6] + red[7];
    return t;
}

// ---------------------------------------------------------------------------
// init: slots = broadcast(slot_mu); emit actS planes (slots feed gh at it0)
// ---------------------------------------------------------------------------
__global__ __launch_bounds__(256) void init_slots_kernel(const float* __restrict__ mu) {
    unsigned idx = blockIdx.x * 256u + threadIdx.x;          // < 262144
    float x = mu[idx & 16383u];
    g_scratch[OFF_SLOTS + idx] = x;
    __nv_bfloat16 h, l; bsplit(x, h, l);
    g_actSh[idx] = h; g_actSl[idx] = l;
}

// ---------------------------------------------------------------------------
// transpose 1024x1024 fp32: in -> g_scratch[dstOff]
// ---------------------------------------------------------------------------
__global__ void transpose_kernel(const float* __restrict__ in, unsigned dstOff) {
    __shared__ float t[32][33];
    int x  = blockIdx.x * 32 + threadIdx.x;
    int y0 = blockIdx.y * 32;
    #pragma unroll
    for (int j = threadIdx.y; j < 32; j += 8)
        t[j][threadIdx.x] = in[(size_t)(y0 + j) * 1024 + x];
    __syncthreads();
    int xo  = blockIdx.y * 32 + threadIdx.x;
    int yo0 = blockIdx.x * 32;
    #pragma unroll
    for (int j = threadIdx.y; j < 32; j += 8)
        g_scratch[dstOff + (size_t)(yo0 + j) * 1024 + xo] = t[threadIdx.x][j];
}

// ---------------------------------------------------------------------------
// tokens -> bf16 hi/lo planes
// ---------------------------------------------------------------------------
__global__ __launch_bounds__(256) void tcnv_kernel(const float* __restrict__ tokens) {
    size_t idx4 = (size_t)blockIdx.x * 256u + threadIdx.x;
    float4 x = ((const float4*)tokens)[idx4];
    __nv_bfloat16 h0,h1,h2,h3,l0,l1,l2,l3;
    bsplit(x.x,h0,l0); bsplit(x.y,h1,l1); bsplit(x.z,h2,l2); bsplit(x.w,h3,l3);
    size_t k = idx4 * 4;
    *(__nv_bfloat162*)(g_tokh + k)     = __nv_bfloat162(h0, h1);
    *(__nv_bfloat162*)(g_tokh + k + 2) = __nv_bfloat162(h2, h3);
    *(__nv_bfloat162*)(g_tokl + k)     = __nv_bfloat162(l0, l1);
    *(__nv_bfloat162*)(g_tokl + k + 2) = __nv_bfloat162(l2, l3);
}

// ---------------------------------------------------------------------------
// split-convert to 2 planes: src (flat fp32) -> dh, dl
// ---------------------------------------------------------------------------
__global__ __launch_bounds__(256) void convw2_kernel(const float* __restrict__ src,
                                                     unsigned srcOff,
                                                     __nv_bfloat16* __restrict__ dh,
                                                     __nv_bfloat16* __restrict__ dl) {
    size_t idx4 = (size_t)blockIdx.x * 256u + threadIdx.x;
    const float* S = src ? src : (g_scratch + srcOff);
    float4 x = *(const float4*)(S + idx4 * 4);
    __nv_bfloat16 h0,h1,h2,h3,l0,l1,l2,l3;
    bsplit(x.x,h0,l0); bsplit(x.y,h1,l1); bsplit(x.z,h2,l2); bsplit(x.w,h3,l3);
    size_t k = idx4 * 4;
    *(__nv_bfloat162*)(dh + k)     = __nv_bfloat162(h0, h1);
    *(__nv_bfloat162*)(dh + k + 2) = __nv_bfloat162(h2, h3);
    *(__nv_bfloat162*)(dl + k)     = __nv_bfloat162(l0, l1);
    *(__nv_bfloat162*)(dl + k + 2) = __nv_bfloat162(l2, l3);
}

// ---------------------------------------------------------------------------
// gemv: out[row] = scale * dot(M[row, 0:len], v)
// ---------------------------------------------------------------------------
__global__ __launch_bounds__(256) void gemv_kernel(const float* __restrict__ M,
                                                   unsigned moff,
                                                   const float* __restrict__ v,
                                                   unsigned outoff, int len, float scale) {
    __shared__ float red[8];
    const float* Mr = (M ? M : g_scratch + moff) + (size_t)blockIdx.x * len;
    int tid = threadIdx.x;
    float p = 0.f;
    for (int i = tid * 4; i < len; i += 1024) {
        float4 a = *(const float4*)(Mr + i);
        float4 b = *(const float4*)(v + i);
        p += a.x*b.x + a.y*b.y + a.z*b.z + a.w*b.w;
    }
    float tot = blk_reduce(p, red, tid);
    if (tid == 0) g_scratch[outoff + blockIdx.x] = scale * tot;
}

// ---------------------------------------------------------------------------
// 2-plane HMMA GEMM: C = (Ah+Al) (.) (Wh+Wl)^T  via Ah*Wh + Ah*Wl + Al*Wh.
// BM in {128, 64, 32}.  BN=64.  256 threads, 4-stage cp.async.
// epi: 0=+bias 2=gelu(+bias) 3=+bias+res(Cres) 4=*SCALE 6=raw
//      7=+bias+brow*bias2  8=+brow*bias
// ---------------------------------------------------------------------------
#define SAP 40

template<int BM>
__device__ __forceinline__ void gemm2_core(char* sm,
    const __nv_bfloat16* __restrict__ Ah, const __nv_bfloat16* __restrict__ Al,
    const __nv_bfloat16* __restrict__ Wh, const __nv_bfloat16* __restrict__ Wl,
    const float* __restrict__ bias, const float* __restrict__ bias2,
    float* Cout, const float* __restrict__ Cres,
    __nv_bfloat16* ph, __nv_bfloat16* pl,
    int N, int K, int epi)
{
    constexpr int NW_M = BM / 32;
    constexpr int WTN  = BM / 4;
    constexpr int NT   = WTN / 8;
    constexpr uint32_t AP  = BM * SAP * 2;
    constexpr uint32_t WP  = 64 * SAP * 2;
    constexpr uint32_t STG = 2 * AP + 2 * WP;

    const int tid  = threadIdx.x;
    const int lane = tid & 31, wid = tid >> 5;
    const int wm = (wid % NW_M) * 32;
    const int wn = (wid / NW_M) * WTN;
    const int bn = blockIdx.x * 64, bm = blockIdx.y * BM;
    const int NC = K >> 5;

    const uint32_t smb = smem_u32(sm);

    const int lrow = tid >> 2, lch = (tid & 3) * 8;
    const uint32_t aoff  = (uint32_t)(lrow * SAP + lch) * 2;
    const uint32_t aoff1 = (uint32_t)((64 + lrow) * SAP + lch) * 2;
    const __nv_bfloat16* agh0 = Ah + (size_t)(bm + (lrow < BM ? lrow : 0)) * K + lch;
    const __nv_bfloat16* agl0 = Al + (size_t)(bm + (lrow < BM ? lrow : 0)) * K + lch;
    const __nv_bfloat16* agh1 = Ah + (size_t)(bm + 64 + lrow) * K + lch;
    const __nv_bfloat16* agl1 = Al + (size_t)(bm + 64 + lrow) * K + lch;
    const __nv_bfloat16* wgh  = Wh + (size_t)(bn + lrow) * K + lch;
    const __nv_bfloat16* wgl  = Wl + (size_t)(bn + lrow) * K + lch;

    const int a_row = wm + (lane & 15);
    const int a_col = (lane >> 4) * 8;
    const int b_row = wn + ((lane >> 4) & 1) * 8 + (lane & 7);
    const int b_col = ((lane >> 3) & 1) * 8;
    const int l2 = lane & 15;
    const int b_row1 = wn + (l2 & 7);
    const int b_col1 = ((l2 >> 3) & 1) * 8;

    float acc[2][NT][4];
    #pragma unroll
    for (int i = 0; i < 2; i++)
        #pragma unroll
        for (int j = 0; j < NT; j++)
            #pragma unroll
            for (int e = 0; e < 4; e++) acc[i][j][e] = 0.f;

    auto load_stage = [&](int st, int c) {
        const uint32_t S = smb + (uint32_t)st * STG;
        const int ko = c * 32;
        if (BM >= 64 || lrow < BM) {
            cp16s(S + aoff, agh0 + ko);
            cp16s(S + AP + aoff, agl0 + ko);
        }
        if (BM == 128) {
            cp16s(S + aoff1, agh1 + ko);
            cp16s(S + AP + aoff1, agl1 + ko);
        }
        cp16s(S + 2 * AP + aoff, wgh + ko);
        cp16s(S + 2 * AP + WP + aoff, wgl + ko);
        cpcommit();
    };

    load_stage(0, 0);
    load_stage(1, 1);
    load_stage(2, 2);

    for (int c = 0; c < NC; c++) {
        int bnd = NC - 1 - c; if (bnd > 2) bnd = 2;
        cpwait_n(bnd);
        __syncthreads();
        if (c + 3 < NC) load_stage((c + 3) & 3, c + 3);
        const uint32_t S = smb + (uint32_t)(c & 3) * STG;
        const uint32_t abh = S, abl = S + AP;
        const uint32_t wbh = S + 2 * AP, wbl = S + 2 * AP + WP;
        #pragma unroll
        for (int ks = 0; ks < 2; ks++) {
            uint32_t afh[2][4], afl[2][4], bfh[2][4], bfl[2][4];
            #pragma unroll
            for (int mt = 0; mt < 2; mt++) {
                uint32_t ao = (uint32_t)(((a_row + mt * 16) * SAP) + ks * 16 + a_col) * 2;
                ldm4(afh[mt], abh + ao);
                ldm4(afl[mt], abl + ao);
            }
            if (NT == 1) {
                uint32_t bo = (uint32_t)((b_row1 * SAP) + ks * 16 + b_col1) * 2;
                ldm2(bfh[0], wbh + bo);
                ldm2(bfl[0], wbl + bo);
            } else {
                #pragma unroll
                for (int nb = 0; nb < NT / 2; nb++) {
                    uint32_t bo = (uint32_t)(((b_row + nb * 16) * SAP) + ks * 16 + b_col) * 2;
                    ldm4(bfh[nb], wbh + bo);
                    ldm4(bfl[nb], wbl + bo);
                }
            }
            #pragma unroll
            for (int mt = 0; mt < 2; mt++)
                #pragma unroll
                for (int nt = 0; nt < NT; nt++) {
                    const uint32_t* bh = &bfh[nt >> 1][(nt & 1) * 2];
                    const uint32_t* bl = &bfl[nt >> 1][(nt & 1) * 2];
                    mma16816(acc[mt][nt], afh[mt], bh);
                    mma16816(acc[mt][nt], afh[mt], bl);
                    mma16816(acc[mt][nt], afl[mt], bh);
                }
        }
    }

    const int mrow = lane >> 2, ncol2 = (lane & 3) * 2;
    #pragma unroll
    for (int mt = 0; mt < 2; mt++) {
        #pragma unroll
        for (int h = 0; h < 2; h++) {
            const int m = bm + wm + mt * 16 + mrow + h * 8;
            float brow = 0.f;
            if (epi == 7 || epi == 8) brow = g_scratch[OFF_BS + m];
            #pragma unroll
            for (int nt = 0; nt < NT; nt++) {
                const int n0 = bn + wn + nt * 8 + ncol2;
                float ox = acc[mt][nt][h * 2], oy = acc[mt][nt][h * 2 + 1];
                if (epi == 4) { ox *= SCALEF; oy *= SCALEF; }
                else if (epi == 6) { }
                else {
                    float2 bb = *(const float2*)(bias + n0);
                    if (epi == 7) {
                        float2 b2 = *(const float2*)(bias2 + n0);
                        ox += bb.x + brow * b2.x; oy += bb.y + brow * b2.y;
                    } else if (epi == 8) {
                        ox += brow * bb.x; oy += brow * bb.y;
                    } else { ox += bb.x; oy += bb.y; }
                    if (epi == 2) { ox = geluf(ox); oy = geluf(oy); }
                    if (epi == 3) {
                        float2 c0 = *(const float2*)(Cres + (size_t)m * N + n0);
                        ox += c0.x; oy += c0.y;
                    }
                }
                if (Cout) *(float2*)(Cout + (size_t)m * N + n0) = make_float2(ox, oy);
                if (ph) {
                    __nv_bfloat16 hx, lx, hy, ly;
                    bsplit(ox, hx, lx); bsplit(oy, hy, ly);
                    *(__nv_bfloat162*)(ph + (size_t)m * N + n0) = __nv_bfloat162(hx, hy);
                    *(__nv_bfloat162*)(pl + (size_t)m * N + n0) = __nv_bfloat162(lx, ly);
                }
            }
        }
    }
}

template<int BM>
__global__ __launch_bounds__(256) void gemm2_k(const __nv_bfloat16* __restrict__ Ah,
                                               const __nv_bfloat16* __restrict__ Al,
                                               const __nv_bfloat16* __restrict__ Wh,
                                               const __nv_bfloat16* __restrict__ Wl,
                                               const float* __restrict__ bias,
                                               const float* __restrict__ bias2,
                                               float* Cout, const float* Cres,
                                               __nv_bfloat16* ph, __nv_bfloat16* pl,
                                               int N, int K, int epi) {
    extern __shared__ char sm[];
    gemm2_core<BM>(sm, Ah, Al, Wh, Wl, bias, bias2, Cout, Cres, ph, pl, N, K, epi);
}

// merged GRU gemms (BM=64: 2 CTAs/SM)
__global__ __launch_bounds__(256) void gru_gemm_k(const float* __restrict__ bih,
                                                  const float* __restrict__ bhh) {
    extern __shared__ char sm[];
    if (blockIdx.z == 0)
        gemm2_core<64>(sm, g_actBh, g_actBl, g_wIh, g_wIh + 3072u*1024u,
                       bih, nullptr, g_scratch + OFF_GI, nullptr,
                       nullptr, nullptr, 3072, 1024, 0);
    else
        gemm2_core<64>(sm, g_actSh, g_actSl, g_wHh, g_wHh + 3072u*1024u,
                       bhh, nullptr, g_scratch + OFF_GH, nullptr,
                       nullptr, nullptr, 3072, 1024, 0);
}

// ---------------------------------------------------------------------------
// Single-read fused pass (256 threads): per 16-token group -- load tok strip
// once, logits (k split over 8 warps) + shfl softmax + updates vs SAME strip.
// U accumulated in registers across groups; one atomicAdd set per CTA.
// grid (32 chunks of 128 tokens, 16 b).
// ---------------------------------------------------------------------------
#define FP_SMEM 198144
__global__ __launch_bounds__(256) void fused_pass_kernel(float* __restrict__ attn_out,
                                                         int wlast) {
    extern __shared__ char sm[];
    __shared__ float Lg[8][16][17];
    __shared__ float Att32[16][17];                 // [token][slot]
    __shared__ __nv_bfloat16 ATh[16][24], ATl[16][24];  // [slot][token]
    __shared__ float cbs[16], rs[16];
    const int tid = threadIdx.x;
    const int lane = tid & 31, wid = tid >> 5;
    const int sc = blockIdx.x, b = blockIdx.y;

    const uint32_t smb = smem_u32(sm);
    const uint32_t Qh = smb, Ql = smb + 33024u;
    const uint32_t TB = smb + 66048u;               // 2 buffers x 66048

    if (tid < 16) { cbs[tid] = g_scratch[OFF_CB + b * 16 + tid]; rs[tid] = 0.f; }

    const size_t tokbase = ((size_t)b * 4096 + (size_t)sc * 128) * 1024;

    auto load_group = [&](int buf, int g) {
        const uint32_t Bs = TB + (uint32_t)buf * 66048u;
        #pragma unroll
        for (int i = 0; i < 8; i++) {
            int idx = tid + 256 * i;
            int row = idx >> 7, j = idx & 127;
            cp16s(Bs + (uint32_t)(row * 1032 + j * 8) * 2,
                  g_tokh + tokbase + (size_t)(g * 16 + row) * 1024 + j * 8);
            cp16s(Bs + 33024u + (uint32_t)(row * 1032 + j * 8) * 2,
                  g_tokl + tokbase + (size_t)(g * 16 + row) * 1024 + j * 8);
        }
        cpcommit();
    };

    // Q planes + first group
    {
        #pragma unroll
        for (int i = 0; i < 8; i++) {
            int id = tid + 256 * i;
            int row = id >> 7, j = id & 127;
            cp16s(Qh + (uint32_t)(row * 1032 + j * 8) * 2,
                  g_q2h + (size_t)(b * 16 + row) * 1024 + j * 8);
            cp16s(Ql + (uint32_t)(row * 1032 + j * 8) * 2,
                  g_q2l + (size_t)(b * 16 + row) * 1024 + j * 8);
        }
        cpcommit();
        load_group(0, 0);
    }

    // persistent U accumulators: warp wid owns d slice [wid*128, wid*128+128)
    float uacc[16][4];
    #pragma unroll
    for (int nt = 0; nt < 16; nt++)
        #pragma unroll
        for (int e = 0; e < 4; e++) uacc[nt][e] = 0.f;

    const int kw = wid * 128;               // this warp's k-slice
    const int a_r = lane & 15;              // token row
    const int a_c = (lane >> 4) * 8;
    const int b_r = ((lane >> 4) & 1) * 8 + (lane & 7);
    const int b_c = ((lane >> 3) & 1) * 8;
    const uint32_t ATHb = smem_u32(&ATh[0][0]);
    const uint32_t ATLb = smem_u32(&ATl[0][0]);
    const uint32_t at_off = (uint32_t)((lane & 15) * 24 + (lane >> 4) * 8) * 2;

    for (int g = 0; g < 8; g++) {
        cpwait_n(0);
        __syncthreads();
        if (g + 1 < 8) load_group((g + 1) & 1, g + 1);
        const uint32_t Bs = TB + (uint32_t)(g & 1) * 66048u;
        const uint32_t Bh = Bs, Bl = Bs + 33024u;

        // ---- logits: warp k-slice, m16 (tokens) x n16 (slots) ----
        float la[2][4];
        #pragma unroll
        for (int nt = 0; nt < 2; nt++)
            #pragma unroll
            for (int e = 0; e < 4; e++) la[nt][e] = 0.f;
        #pragma unroll
        for (int ks = 0; ks < 8; ks++) {
            const int col = kw + ks * 16;
            uint32_t afh[4], afl[4], bfh[4], bfl[4];
            uint32_t ao = (uint32_t)(a_r * 1032 + col + a_c) * 2;
            ldm4(afh, Bh + ao);
            ldm4(afl, Bl + ao);
            uint32_t bo = (uint32_t)(b_r * 1032 + col + b_c) * 2;
            ldm4(bfh, Qh + bo);
            ldm4(bfl, Ql + bo);
            #pragma unroll
            for (int nt = 0; nt < 2; nt++) {
                mma16816(la[nt], afh, &bfh[nt * 2]);
                mma16816(la[nt], afh, &bfl[nt * 2]);
                mma16816(la[nt], afl, &bfh[nt * 2]);
            }
        }
        #pragma unroll
        for (int nt = 0; nt < 2; nt++)
            #pragma unroll
            for (int e = 0; e < 4; e++) {
                int row = (lane >> 2) + (e >> 1) * 8;
                int col = nt * 8 + (lane & 3) * 2 + (e & 1);
                Lg[wid][row][col] = la[nt][e];
            }
        __syncthreads();

        // ---- fused reduce + parallel softmax (256 thr = 16 tok x 16 slot) ----
        {
            int tok = tid >> 4, s = tid & 15;
            float v = cbs[s];
            #pragma unroll
            for (int w = 0; w < 8; w++) v += Lg[w][tok][s];
            float mx = v;
            #pragma unroll
            for (int o = 8; o > 0; o >>= 1)
                mx = fmaxf(mx, __shfl_xor_sync(0xffffffffu, mx, o));
            float e = __expf(v - mx);
            float sum = e;
            #pragma unroll
            for (int o = 8; o > 0; o >>= 1)
                sum += __shfl_xor_sync(0xffffffffu, sum, o);
            float a = e / sum;
            Att32[tok][s] = a;
            __nv_bfloat16 h, l; bsplit(a, h, l);
            ATh[s][tok] = h; ATl[s][tok] = l;
            if (wlast)
                attn_out[(size_t)(b * 16 + s) * 4096 + (size_t)sc * 128 + g * 16 + tok] = a;
        }
        __syncthreads();

        // rowsum partial (threads 16..31, slot = tid-16)
        if (tid >= 16 && tid < 32) {
            int s = tid - 16;
            float t = 0.f;
            #pragma unroll
            for (int tok = 0; tok < 16; tok++) t += Att32[tok][s];
            rs[s] += t;
        }

        // ---- updates: U[slots][d-slice] += attnT @ tok  (same strip) ----
        uint32_t ath[4], atl[4];
        ldm4(ath, ATHb + at_off);
        ldm4(atl, ATLb + at_off);
        #pragma unroll
        for (int nt = 0; nt < 16; nt++) {
            const int d0 = kw + nt * 8;
            uint32_t bh[2], bl[2];
            uint32_t bo = (uint32_t)((lane & 15) * 1032 + d0) * 2;
            ldm2t(bh, Bh + bo);
            ldm2t(bl, Bl + bo);
            mma16816(uacc[nt], ath, bh);
            mma16816(uacc[nt], ath, bl);
            mma16816(uacc[nt], atl, bh);
        }
    }

    __syncthreads();
    if (tid < 16)
        g_scratch[OFF_RP + (size_t)(b * 16 + tid) * 32 + sc] = rs[tid];

    // one atomic accumulation per CTA
    float* Ub = g_scratch + OFF_U + (size_t)(b * 16) * 1024;
    const int slot0 = lane >> 2;
    #pragma unroll
    for (int nt = 0; nt < 16; nt++) {
        const int d0 = kw + nt * 8 + (lane & 3) * 2;
        atomicAdd(&Ub[(size_t)slot0 * 1024 + d0],           uacc[nt][0]);
        atomicAdd(&Ub[(size_t)slot0 * 1024 + d0 + 1],       uacc[nt][1]);
        atomicAdd(&Ub[(size_t)(slot0 + 8) * 1024 + d0],     uacc[nt][2]);
        atomicAdd(&Ub[(size_t)(slot0 + 8) * 1024 + d0 + 1], uacc[nt][3]);
    }
}

// ---------------------------------------------------------------------------
// LayerNorm (slots) -> actA planes; docb=1: also cb + zero-U.  shfl reductions.
// ---------------------------------------------------------------------------
__global__ __launch_bounds__(256) void ln_kernel(unsigned offX,
                                                 const float* __restrict__ g,
                                                 const float* __restrict__ bt,
                                                 int docb) {
    __shared__ float red[8];
    const float* X = g_scratch + offX;
    int row = blockIdx.x, tid = threadIdx.x;
    float4 x = ((const float4*)X)[row * 256 + tid];
    float mean = blk_reduce(x.x + x.y + x.z + x.w, red, tid) * (1.0f / 1024.0f);
    float4 dx = { x.x - mean, x.y - mean, x.z - mean, x.w - mean };
    __syncthreads();
    float var = blk_reduce(dx.x*dx.x + dx.y*dx.y + dx.z*dx.z + dx.w*dx.w, red, tid)
                * (1.0f / 1024.0f);
    float rsv = rsqrtf(var + EPS_LN);
    float4 gg = ((const float4*)g)[tid], bb = ((const float4*)bt)[tid];
    float y[4] = { dx.x*rsv*gg.x + bb.x, dx.y*rsv*gg.y + bb.y,
                   dx.z*rsv*gg.z + bb.z, dx.w*rsv*gg.w + bb.w };
    size_t base = (size_t)row * 1024u + tid * 4;
    #pragma unroll
    for (int j = 0; j < 4; j++) {
        __nv_bfloat16 h, l; bsplit(y[j], h, l);
        g_actAh[base + j] = h; g_actAl[base + j] = l;
    }
    if (docb) {
        *(float4*)&g_scratch[OFF_U + base] = make_float4(0.f, 0.f, 0.f, 0.f);
        float p = 0.f;
        #pragma unroll
        for (int j = 0; j < 4; j++) p += y[j] * g_scratch[OFF_WCB + tid * 4 + j];
        __syncthreads();
        float tot = blk_reduce(p, red, tid);
        if (tid == 0)
            g_scratch[OFF_CB + row] = SCALEF * (tot + g_scratch[OFF_C0]);
    }
}

// ---------------------------------------------------------------------------
// reduceU (+rowsum): Un[row] = U[row]/rowsum -> actA planes; BS=brow
// ---------------------------------------------------------------------------
__global__ __launch_bounds__(256) void reduceU_kernel() {
    float* S = g_scratch;
    int row = blockIdx.x, tid = threadIdx.x;
    float s = 0.f;
    #pragma unroll
    for (int cc = 0; cc < 32; cc++) s += S[OFF_RP + (size_t)row * 32 + cc];
    float ri = 1.0f / (s + EPS_ATTN);
    if (tid == 0) S[OFF_BS + row] = s * ri;
    size_t base = (size_t)row * 1024u + tid * 4;
    float4 v = *(const float4*)&S[OFF_U + base];
    float y[4] = { v.x * ri, v.y * ri, v.z * ri, v.w * ri };
    #pragma unroll
    for (int j = 0; j < 4; j++) {
        __nv_bfloat16 h, l; bsplit(y[j], h, l);
        g_actAh[base + j] = h; g_actAl[base + j] = l;
    }
}

// ---------------------------------------------------------------------------
// Fused GRU combine + LayerNorm(mlp) -> slots, actA planes.  shfl reductions.
// ---------------------------------------------------------------------------
__global__ __launch_bounds__(256) void gru_ln_kernel(const float* __restrict__ gm,
                                                     const float* __restrict__ bm) {
    __shared__ float red[8];
    float* S = g_scratch;
    int row = blockIdx.x, tid = threadIdx.x;
    size_t gb = (size_t)row * 3072 + tid * 4;
    float4 ir = *(const float4*)&S[OFF_GI + gb];
    float4 iz = *(const float4*)&S[OFF_GI + gb + 1024];
    float4 in_ = *(const float4*)&S[OFF_GI + gb + 2048];
    float4 hr = *(const float4*)&S[OFF_GH + gb];
    float4 hz = *(const float4*)&S[OFF_GH + gb + 1024];
    float4 hn = *(const float4*)&S[OFF_GH + gb + 2048];
    float4 sp = *(const float4*)&S[OFF_SLOTS + (size_t)row * 1024 + tid * 4];
    float ns[4];
    {
        float r0 = sigmf(ir.x + hr.x), z0 = sigmf(iz.x + hz.x);
        ns[0] = (1.f - z0) * tanhf(in_.x + r0 * hn.x) + z0 * sp.x;
        float r1 = sigmf(ir.y + hr.y), z1 = sigmf(iz.y + hz.y);
        ns[1] = (1.f - z1) * tanhf(in_.y + r1 * hn.y) + z1 * sp.y;
        float r2 = sigmf(ir.z + hr.z), z2 = sigmf(iz.z + hz.z);
        ns[2] = (1.f - z2) * tanhf(in_.z + r2 * hn.z) + z2 * sp.z;
        float r3 = sigmf(ir.w + hr.w), z3 = sigmf(iz.w + hz.w);
        ns[3] = (1.f - z3) * tanhf(in_.w + r3 * hn.w) + z3 * sp.w;
    }
    *(float4*)&S[OFF_SLOTS + (size_t)row * 1024 + tid * 4] =
        make_float4(ns[0], ns[1], ns[2], ns[3]);
    float mean = blk_reduce(ns[0] + ns[1] + ns[2] + ns[3], red, tid) * (1.0f / 1024.0f);
    float dx[4] = { ns[0]-mean, ns[1]-mean, ns[2]-mean, ns[3]-mean };
    __syncthreads();
    float var = blk_reduce(dx[0]*dx[0] + dx[1]*dx[1] + dx[2]*dx[2] + dx[3]*dx[3], red, tid)
                * (1.0f / 1024.0f);
    float rsv = rsqrtf(var + EPS_LN);
    float4 gg = ((const float4*)gm)[tid], bb = ((const float4*)bm)[tid];
    float y[4] = { dx[0]*rsv*gg.x + bb.x, dx[1]*rsv*gg.y + bb.y,
                   dx[2]*rsv*gg.z + bb.z, dx[3]*rsv*gg.w + bb.w };
    size_t base = (size_t)row * 1024u + tid * 4;
    #pragma unroll
    for (int j = 0; j < 4; j++) {
        __nv_bfloat16 h, l; bsplit(y[j], h, l);
        g_actAh[base + j] = h; g_actAl[base + j] = l;
    }
}

// ---------------------------------------------------------------------------
// copy slots -> out (fallback only)
// ---------------------------------------------------------------------------
__global__ __launch_bounds__(256) void copy_out_kernel(float* __restrict__ out, int n) {
    int idx = blockIdx.x * 256 + threadIdx.x;
    if (idx < n) out[idx] = g_scratch[OFF_SLOTS + idx];
}

// ---------------------------------------------------------------------------
// host
// ---------------------------------------------------------------------------
#define SMEM128 (4 * (2*128 + 2*64) * SAP * 2)   /* 122880 */
#define SMEM64  (4 * (2*64 + 2*64) * SAP * 2)    /* 81920 */
#define SMEM32  (4 * (2*32 + 2*64) * SAP * 2)    /* 61440 */

extern "C" void kernel_launch(void* const* d_in, const int* in_sizes, int n_in,
                              void* d_out, int out_size) {
    const float* tokens = (const float*)d_in[0];
    const float* mu     = (const float*)d_in[1];
    const float* Wq  = (const float*)d_in[2];  const float* bq  = (const float*)d_in[3];
    const float* Wk  = (const float*)d_in[4];  const float* bk  = (const float*)d_in[5];
    const float* Wv  = (const float*)d_in[6];  const float* bv  = (const float*)d_in[7];
    const float* Wih = (const float*)d_in[8];  const float* bih = (const float*)d_in[9];
    const float* Whh = (const float*)d_in[10]; const float* bhh = (const float*)d_in[11];
    const float* W1  = (const float*)d_in[12]; const float* b1  = (const float*)d_in[13];
    const float* W2  = (const float*)d_in[14]; const float* b2  = (const float*)d_in[15];
    const float* gs  = (const float*)d_in[16]; const float* bs  = (const float*)d_in[17];
    const float* gm  = (const float*)d_in[18]; const float* bm  = (const float*)d_in[19];
    float* out = (float*)d_out;

    cudaFuncSetAttribute((const void*)gemm2_k<128>, cudaFuncAttributeMaxDynamicSharedMemorySize, SMEM128);
    cudaFuncSetAttribute((const void*)gemm2_k<64>,  cudaFuncAttributeMaxDynamicSharedMemorySize, SMEM64);
    cudaFuncSetAttribute((const void*)gemm2_k<32>,  cudaFuncAttributeMaxDynamicSharedMemorySize, SMEM32);
    cudaFuncSetAttribute((const void*)gru_gemm_k,   cudaFuncAttributeMaxDynamicSharedMemorySize, SMEM64);
    cudaFuncSetAttribute((const void*)fused_pass_kernel, cudaFuncAttributeMaxDynamicSharedMemorySize, FP_SMEM);

    __nv_bfloat16 *wMw, *wV, *wIh, *wHh, *w1, *w2, *wWqT, *wWkT;
    __nv_bfloat16 *actAh, *actAl, *actBh, *actBl, *q2h, *q2l, *actSh, *actSl;
    cudaGetSymbolAddress((void**)&wMw,  g_wMw);
    cudaGetSymbolAddress((void**)&wV,   g_wV);
    cudaGetSymbolAddress((void**)&wIh,  g_wIh);
    cudaGetSymbolAddress((void**)&wHh,  g_wHh);
    cudaGetSymbolAddress((void**)&w1,   g_w1);
    cudaGetSymbolAddress((void**)&w2,   g_w2);
    cudaGetSymbolAddress((void**)&wWqT, g_wWqT);
    cudaGetSymbolAddress((void**)&wWkT, g_wWkT);
    cudaGetSymbolAddress((void**)&actAh, g_actAh);
    cudaGetSymbolAddress((void**)&actAl, g_actAl);
    cudaGetSymbolAddress((void**)&actBh, g_actBh);
    cudaGetSymbolAddress((void**)&actBl, g_actBl);
    cudaGetSymbolAddress((void**)&q2h, g_q2h);
    cudaGetSymbolAddress((void**)&q2l, g_q2l);
    cudaGetSymbolAddress((void**)&actSh, g_actSh);
    cudaGetSymbolAddress((void**)&actSl, g_actSl);
    float* scr;
    cudaGetSymbolAddress((void**)&scr, g_scratch);

    const int direct_out = (out_size >= 262144);
    float* attnp = (out_size >= 1310720) ? (out + 262144) : (scr + OFF_ATTN);

    const size_t P1M = 1024u * 1024u;
    const size_t P3M = 3072u * 1024u;
    const size_t P4M = 4096u * 1024u;

    // ---- one-time ----
    transpose_kernel<<<dim3(32, 32), dim3(32, 8)>>>(Wk, OFF_WKT);
    transpose_kernel<<<dim3(32, 32), dim3(32, 8)>>>(Wq, OFF_WQT);
    tcnv_kernel<<<65536, 256>>>(tokens);
    convw2_kernel<<<1024, 256>>>(nullptr, OFF_WQT, wWqT, wWqT + P1M);
    convw2_kernel<<<1024, 256>>>(nullptr, OFF_WKT, wWkT, wWkT + P1M);
    convw2_kernel<<<1024, 256>>>(Wv,  0, wV,  wV + P1M);
    convw2_kernel<<<3072, 256>>>(Wih, 0, wIh, wIh + P3M);
    gemv_kernel<<<1024, 256>>>(nullptr, OFF_WQT, bk, OFF_WCB, 1024, 1.0f);
    gemv_kernel<<<1024, 256>>>(nullptr, OFF_WKT, bq, OFF_V2, 1024, SCALEF);
    gemv_kernel<<<1, 256>>>(bq, 0, bk, OFF_C0, 1024, 1.0f);
    // Mw = SCALE * WkT (.) WqT^T   [1024 x 1024]
    gemm2_k<128><<<dim3(16, 8), 256, SMEM128>>>(wWkT, wWkT + P1M, wWqT, wWqT + P1M,
                                                nullptr, nullptr, scr + OFF_MFP, nullptr,
                                                nullptr, nullptr, 1024, 1024, 4);
    convw2_kernel<<<1024, 256>>>(nullptr, OFF_MFP, wMw, wMw + P1M);
    convw2_kernel<<<3072, 256>>>(Whh, 0, wHh, wHh + P3M);
    convw2_kernel<<<4096, 256>>>(W1,  0, w1,  w1 + P4M);
    convw2_kernel<<<4096, 256>>>(W2,  0, w2,  w2 + P4M);
    init_slots_kernel<<<1024, 256>>>(mu);

    for (int it = 0; it < 3; it++) {
        const int last = (it == 2);
        ln_kernel<<<256, 256>>>(OFF_SLOTS, gs, bs, 1);
        gemm2_k<32><<<dim3(16, 8), 256, SMEM32>>>(actAh, actAl, wMw, wMw + P1M,
                                                  scr + OFF_V2, nullptr, nullptr, nullptr,
                                                  q2h, q2l, 1024, 1024, 0);
        fused_pass_kernel<<<dim3(32, 16), 256, FP_SMEM>>>(attnp, last);
        reduceU_kernel<<<256, 256>>>();
        // upd = Un @ Wv^T + brow*bv  -> actB planes
        gemm2_k<32><<<dim3(16, 8), 256, SMEM32>>>(actAh, actAl, wV, wV + P1M,
                                                  bv, nullptr, nullptr, nullptr,
                                                  actBh, actBl, 1024, 1024, 8);
        gru_gemm_k<<<dim3(48, 4, 2), 256, SMEM64>>>(bih, bhh);
        gru_ln_kernel<<<256, 256>>>(gm, bm);
        gemm2_k<64><<<dim3(64, 4), 256, SMEM64>>>(actAh, actAl, w1, w1 + P4M,
                                                  b1, nullptr, nullptr, nullptr,
                                                  actBh, actBl, 4096, 1024, 2);
        float* w2dst = (last && direct_out) ? out : (scr + OFF_SLOTS);
        gemm2_k<32><<<dim3(16, 8), 256, SMEM32>>>(actBh, actBl, w2, w2 + P4M,
                                                  b2, nullptr, w2dst, scr + OFF_SLOTS,
                                                  last ? nullptr : actSh,
                                                  last ? nullptr : actSl,
                                                  1024, 4096, 3);
    }

    if (!direct_out) {
        int nslots = out_size < 262144 ? out_size : 262144;
        copy_out_kernel<<<1024, 256>>>(out, nslots);
    }
}